// round 3
// baseline (speedup 1.0000x reference)
#include <cuda_runtime.h>
#include <cuda_bf16.h>
#include <cstdint>

#define B_ROWS 32768
#define C_COLS 1000
#define C_PAD  1024
#define F_DIM  256

// Scratch (device globals — no allocation allowed)
__device__ __align__(16) __nv_bfloat16 g_Fn[(size_t)B_ROWS * F_DIM]; // normalized features, bf16
__device__ __align__(16) __nv_bfloat16 g_Pn[(size_t)C_PAD * F_DIM];  // normalized prototypes, padded
__device__ float g_rowsum[B_ROWS];

// ---------------------------------------------------------------------------
// Kernel 1: L2-normalize features -> bf16; zero rowsum
// One warp per row (256 floats = 8 per lane).
// ---------------------------------------------------------------------------
__global__ void norm_features_kernel(const float* __restrict__ feat) {
    int gtid = blockIdx.x * blockDim.x + threadIdx.x;
    if (gtid < B_ROWS) g_rowsum[gtid] = 0.0f;

    int row  = gtid >> 5;
    int lane = gtid & 31;
    if (row >= B_ROWS) return;

    const float4* src = reinterpret_cast<const float4*>(feat + (size_t)row * F_DIM);
    float4 v0 = src[lane * 2 + 0];
    float4 v1 = src[lane * 2 + 1];

    float ss = v0.x*v0.x + v0.y*v0.y + v0.z*v0.z + v0.w*v0.w
             + v1.x*v1.x + v1.y*v1.y + v1.z*v1.z + v1.w*v1.w;
    #pragma unroll
    for (int o = 16; o; o >>= 1) ss += __shfl_xor_sync(0xFFFFFFFFu, ss, o);

    float inv = 1.0f / fmaxf(sqrtf(ss), 1e-12f);

    union { __nv_bfloat162 h[4]; uint4 u; } pack;
    pack.h[0] = __floats2bfloat162_rn(v0.x*inv, v0.y*inv);
    pack.h[1] = __floats2bfloat162_rn(v0.z*inv, v0.w*inv);
    pack.h[2] = __floats2bfloat162_rn(v1.x*inv, v1.y*inv);
    pack.h[3] = __floats2bfloat162_rn(v1.z*inv, v1.w*inv);

    reinterpret_cast<uint4*>(g_Fn)[row * (F_DIM/8) + lane] = pack.u;
}

// ---------------------------------------------------------------------------
// Kernel 2: L2-normalize prototypes -> bf16, zero-pad rows [1000,1024)
// ---------------------------------------------------------------------------
__global__ void norm_protos_kernel(const float* __restrict__ proto) {
    int gtid = blockIdx.x * blockDim.x + threadIdx.x;
    int row  = gtid >> 5;
    int lane = gtid & 31;
    if (row >= C_PAD) return;

    if (row >= C_COLS) {
        uint4 z = {0u, 0u, 0u, 0u};
        reinterpret_cast<uint4*>(g_Pn)[row * (F_DIM/8) + lane] = z;
        return;
    }

    const float4* src = reinterpret_cast<const float4*>(proto + (size_t)row * F_DIM);
    float4 v0 = src[lane * 2 + 0];
    float4 v1 = src[lane * 2 + 1];

    float ss = v0.x*v0.x + v0.y*v0.y + v0.z*v0.z + v0.w*v0.w
             + v1.x*v1.x + v1.y*v1.y + v1.z*v1.z + v1.w*v1.w;
    #pragma unroll
    for (int o = 16; o; o >>= 1) ss += __shfl_xor_sync(0xFFFFFFFFu, ss, o);

    float inv = 1.0f / fmaxf(sqrtf(ss), 1e-12f);

    union { __nv_bfloat162 h[4]; uint4 u; } pack;
    pack.h[0] = __floats2bfloat162_rn(v0.x*inv, v0.y*inv);
    pack.h[1] = __floats2bfloat162_rn(v0.z*inv, v0.w*inv);
    pack.h[2] = __floats2bfloat162_rn(v1.x*inv, v1.y*inv);
    pack.h[3] = __floats2bfloat162_rn(v1.z*inv, v1.w*inv);

    reinterpret_cast<uint4*>(g_Pn)[row * (F_DIM/8) + lane] = pack.u;
}

// ---------------------------------------------------------------------------
// Kernel 3: GEMM (cos = Fn @ Pn^T) + epilogue iso = |ds|*sqrt(max(1-cos,0))
// BM=128, BN=128, K=256 fully SMEM-resident (128KB, XOR-swizzled).
// 8 warps: wm in {0,1} (64 rows each), wn in {0..3} (32 cols each).
// Warp tile 64x32 = 4 mtiles x 4 ntiles of m16n8k16 bf16 mma.
// Writes iso to out, accumulates per-row sums into g_rowsum.
// ---------------------------------------------------------------------------
__device__ __forceinline__ void ldsm_x4(uint32_t* r, uint32_t addr) {
    asm volatile("ldmatrix.sync.aligned.m8n8.x4.shared.b16 {%0,%1,%2,%3}, [%4];\n"
        : "=r"(r[0]), "=r"(r[1]), "=r"(r[2]), "=r"(r[3]) : "r"(addr));
}

__device__ __forceinline__ void mma16816(float* c, const uint32_t* a, uint32_t b0, uint32_t b1) {
    asm volatile(
        "mma.sync.aligned.m16n8k16.row.col.f32.bf16.bf16.f32 "
        "{%0,%1,%2,%3}, {%4,%5,%6,%7}, {%8,%9}, {%0,%1,%2,%3};\n"
        : "+f"(c[0]), "+f"(c[1]), "+f"(c[2]), "+f"(c[3])
        : "r"(a[0]), "r"(a[1]), "r"(a[2]), "r"(a[3]), "r"(b0), "r"(b1));
}

__global__ void gemm_epi_kernel(const float* __restrict__ dscale, float* __restrict__ out) {
    extern __shared__ __align__(16) unsigned char smem_raw[];
    // A tile: 128 rows x 512 bytes (swizzled).  B tile: 128 rows x 512 bytes.
    unsigned char* sA = smem_raw;
    unsigned char* sB = smem_raw + 128 * 512;

    const int tid  = threadIdx.x;
    const int lane = tid & 31;
    const int warp = tid >> 5;
    const int wm   = warp & 1;
    const int wn   = warp >> 1;

    // ---- Load A tile (128x256 bf16) ----
    {
        const uint4* gA = reinterpret_cast<const uint4*>(g_Fn);
        size_t rowBase = (size_t)blockIdx.y * 128;
        #pragma unroll
        for (int i = tid; i < 128 * 32; i += 256) {
            int r = i >> 5, c = i & 31;
            uint4 v = gA[(rowBase + r) * 32 + c];
            *reinterpret_cast<uint4*>(sA + r * 512 + ((c ^ (r & 7)) << 4)) = v;
        }
    }
    // ---- Load B tile (128x256 bf16) ----
    {
        const uint4* gB = reinterpret_cast<const uint4*>(g_Pn);
        size_t rowBase = (size_t)blockIdx.x * 128;
        #pragma unroll
        for (int i = tid; i < 128 * 32; i += 256) {
            int r = i >> 5, c = i & 31;
            uint4 v = gB[(rowBase + r) * 32 + c];
            *reinterpret_cast<uint4*>(sB + r * 512 + ((c ^ (r & 7)) << 4)) = v;
        }
    }
    __syncthreads();

    // ---- Precompute ldmatrix lane addresses ----
    uint32_t sA_addr = (uint32_t)__cvta_generic_to_shared(sA);
    uint32_t sB_addr = (uint32_t)__cvta_generic_to_shared(sB);

    int a_r = lane & 15;
    int a_h = lane >> 4;               // which 16B half of the 32B k-chunk pair
    uint32_t aBase[4]; int aXor[4];
    #pragma unroll
    for (int mt = 0; mt < 4; mt++) {
        int row = wm * 64 + mt * 16 + a_r;
        aBase[mt] = sA_addr + row * 512;
        aXor[mt]  = row & 7;
    }
    int b_n = (lane & 7) | ((lane & 16) >> 1);  // n offset 0..15
    int b_h = (lane >> 3) & 1;
    uint32_t bBase[2]; int bXor[2];
    #pragma unroll
    for (int p = 0; p < 2; p++) {
        int n = wn * 32 + p * 16 + b_n;
        bBase[p] = sB_addr + n * 512;
        bXor[p]  = n & 7;
    }

    float acc[4][4][4];
    #pragma unroll
    for (int mt = 0; mt < 4; mt++)
        #pragma unroll
        for (int nt = 0; nt < 4; nt++)
            #pragma unroll
            for (int i = 0; i < 4; i++) acc[mt][nt][i] = 0.0f;

    // ---- Main loop: 16 k-steps of k=16 ----
    #pragma unroll 4
    for (int k = 0; k < 16; k++) {
        uint32_t af[4][4];
        #pragma unroll
        for (int mt = 0; mt < 4; mt++) {
            int chunk = 2 * k + a_h;
            ldsm_x4(af[mt], aBase[mt] + ((chunk ^ aXor[mt]) << 4));
        }
        uint32_t bf[2][4];
        #pragma unroll
        for (int p = 0; p < 2; p++) {
            int chunk = 2 * k + b_h;
            ldsm_x4(bf[p], bBase[p] + ((chunk ^ bXor[p]) << 4));
        }
        #pragma unroll
        for (int mt = 0; mt < 4; mt++)
            #pragma unroll
            for (int nt = 0; nt < 4; nt++) {
                int p = nt >> 1, q = (nt & 1) * 2;
                mma16816(acc[mt][nt], af[mt], bf[p][q], bf[p][q + 1]);
            }
    }

    // ---- Epilogue: iso = |ds| * sqrt(max(1 - cos, 0)); write + row sums ----
    __syncthreads();               // done with SMEM tiles; reuse sA for row sums
    float* srow = reinterpret_cast<float*>(smem_raw);
    if (tid < 128) srow[tid] = 0.0f;
    __syncthreads();

    float ads = fabsf(__ldg(dscale));
    int gcol0 = blockIdx.x * 128 + wn * 32;
    int grow0 = blockIdx.y * 128 + wm * 64;
    int tr = lane >> 2;
    int tc = (lane & 3) * 2;

    #pragma unroll
    for (int mt = 0; mt < 4; mt++) {
        float rs0 = 0.0f, rs1 = 0.0f;
        int row0 = grow0 + mt * 16 + tr;
        int row1 = row0 + 8;
        #pragma unroll
        for (int nt = 0; nt < 4; nt++) {
            int col = gcol0 + nt * 8 + tc;
            if (col < C_COLS) {   // col even, C_COLS even -> col+1 also valid
                float d0 = ads * sqrtf(fmaxf(1.0f - acc[mt][nt][0], 0.0f));
                float d1 = ads * sqrtf(fmaxf(1.0f - acc[mt][nt][1], 0.0f));
                float d2 = ads * sqrtf(fmaxf(1.0f - acc[mt][nt][2], 0.0f));
                float d3 = ads * sqrtf(fmaxf(1.0f - acc[mt][nt][3], 0.0f));
                float2 w0 = {d0, d1};
                float2 w1 = {d2, d3};
                *reinterpret_cast<float2*>(out + (size_t)row0 * C_COLS + col) = w0;
                *reinterpret_cast<float2*>(out + (size_t)row1 * C_COLS + col) = w1;
                rs0 += d0 + d1;
                rs1 += d2 + d3;
            }
        }
        // reduce across the 4 lanes sharing a row (lanes differ only in bits 0-1)
        rs0 += __shfl_xor_sync(0xFFFFFFFFu, rs0, 1);
        rs0 += __shfl_xor_sync(0xFFFFFFFFu, rs0, 2);
        rs1 += __shfl_xor_sync(0xFFFFFFFFu, rs1, 1);
        rs1 += __shfl_xor_sync(0xFFFFFFFFu, rs1, 2);
        if ((lane & 3) == 0) {
            atomicAdd(&srow[wm * 64 + mt * 16 + tr], rs0);
            atomicAdd(&srow[wm * 64 + mt * 16 + tr + 8], rs1);
        }
    }
    __syncthreads();
    if (tid < 128) atomicAdd(&g_rowsum[blockIdx.y * 128 + tid], srow[tid]);
}

// ---------------------------------------------------------------------------
// Kernel 4: out = -(iso + rowsum/1000) / temperature   (float4 vectorized)
// ---------------------------------------------------------------------------
__global__ void finalize_kernel(float* __restrict__ out, const float* __restrict__ temp) {
    size_t i4 = (size_t)blockIdx.x * blockDim.x + threadIdx.x;
    const size_t total4 = (size_t)B_ROWS * C_COLS / 4;
    if (i4 >= total4) return;

    float it = 1.0f / __ldg(temp);
    float4 v = reinterpret_cast<float4*>(out)[i4];
    size_t row = (i4 * 4) / C_COLS;           // 1000 % 4 == 0: no straddle
    float m = g_rowsum[row] * (1.0f / (float)C_COLS);

    v.x = -(v.x + m) * it;
    v.y = -(v.y + m) * it;
    v.z = -(v.z + m) * it;
    v.w = -(v.w + m) * it;
    reinterpret_cast<float4*>(out)[i4] = v;
}

// ---------------------------------------------------------------------------
extern "C" void kernel_launch(void* const* d_in, const int* in_sizes, int n_in,
                              void* d_out, int out_size) {
    const float* feat  = (const float*)d_in[0];
    const float* proto = (const float*)d_in[1];
    const float* dsc   = (const float*)d_in[2];
    const float* temp  = (const float*)d_in[3];
    float* out = (float*)d_out;

    cudaFuncSetAttribute(gemm_epi_kernel,
                         cudaFuncAttributeMaxDynamicSharedMemorySize, 131072);

    norm_features_kernel<<<B_ROWS / 8, 256>>>(feat);          // 4096 blocks
    norm_protos_kernel<<<C_PAD / 8, 256>>>(proto);            // 128 blocks
    gemm_epi_kernel<<<dim3(C_PAD / 128, B_ROWS / 128), 256, 131072>>>(dsc, out);
    finalize_kernel<<<(B_ROWS * C_COLS / 4 + 255) / 256, 256>>>(out, temp);
}

// round 8
// speedup vs baseline: 1.3634x; 1.3634x over previous
#include <cuda_runtime.h>
#include <cuda_bf16.h>
#include <cstdint>

#define B_ROWS 32768
#define C_COLS 1000
#define C_PAD  1024
#define F_DIM  256

#define BM      32      // output rows per CTA
#define BNC     128     // B chunk rows (output cols) per stage
#define NCHUNK  8       // 1024 / 128
#define THREADS 512     // 16 warps

// SMEM layout (dynamic)
#define SM_A     0                       // 32 rows x 512B swizzled      = 16KB
#define SM_SROW  16384                   // 32 floats row sums
#define SM_B0    17408                   // chunk buffer 0: 128 x 512B   = 64KB
#define SM_B1    (17408 + 65536)         // chunk buffer 1               = 64KB
#define SM_STAGE 17408                   // reuses B0+B1: 32 x 4096B     = 128KB
#define SM_TOTAL (17408 + 131072)        // 148480 B

// Scratch (device globals — no allocation allowed)
__device__ __align__(16) __nv_bfloat16 g_Fn[(size_t)B_ROWS * F_DIM];
__device__ __align__(16) __nv_bfloat16 g_Pn[(size_t)C_PAD * F_DIM];

// ---------------------------------------------------------------------------
// helpers
// ---------------------------------------------------------------------------
__device__ __forceinline__ uint32_t smem_u32(const void* p) {
    uint32_t a;
    asm("{ .reg .u64 t; cvta.to.shared.u64 t, %1; cvt.u32.u64 %0, t; }" : "=r"(a) : "l"(p));
    return a;
}
__device__ __forceinline__ void ldsm_x4(uint32_t* r, uint32_t addr) {
    asm volatile("ldmatrix.sync.aligned.m8n8.x4.shared.b16 {%0,%1,%2,%3}, [%4];\n"
        : "=r"(r[0]), "=r"(r[1]), "=r"(r[2]), "=r"(r[3]) : "r"(addr));
}
__device__ __forceinline__ void mma16816(float* c, const uint32_t* a, uint32_t b0, uint32_t b1) {
    asm volatile(
        "mma.sync.aligned.m16n8k16.row.col.f32.bf16.bf16.f32 "
        "{%0,%1,%2,%3}, {%4,%5,%6,%7}, {%8,%9}, {%0,%1,%2,%3};\n"
        : "+f"(c[0]), "+f"(c[1]), "+f"(c[2]), "+f"(c[3])
        : "r"(a[0]), "r"(a[1]), "r"(a[2]), "r"(a[3]), "r"(b0), "r"(b1));
}
__device__ __forceinline__ float fsqrt_ap(float x) {
    float r; asm("sqrt.approx.f32 %0, %1;" : "=f"(r) : "f"(x)); return r;
}
#define CP_ASYNC16(dst, src) \
    asm volatile("cp.async.cg.shared.global [%0], [%1], 16;" :: "r"(dst), "l"(src))
#define CP_COMMIT() asm volatile("cp.async.commit_group;" ::: "memory")
#define CP_WAIT0()  asm volatile("cp.async.wait_group 0;" ::: "memory")

// ---------------------------------------------------------------------------
// Kernel 1: L2-normalize features -> bf16 (one warp per row)
// ---------------------------------------------------------------------------
__global__ void norm_features_kernel(const float* __restrict__ feat) {
    int gtid = blockIdx.x * blockDim.x + threadIdx.x;
    int row  = gtid >> 5;
    int lane = gtid & 31;
    if (row >= B_ROWS) return;

    const float4* src = reinterpret_cast<const float4*>(feat + (size_t)row * F_DIM);
    float4 v0 = src[lane * 2 + 0];
    float4 v1 = src[lane * 2 + 1];

    float ss = v0.x*v0.x + v0.y*v0.y + v0.z*v0.z + v0.w*v0.w
             + v1.x*v1.x + v1.y*v1.y + v1.z*v1.z + v1.w*v1.w;
    #pragma unroll
    for (int o = 16; o; o >>= 1) ss += __shfl_xor_sync(0xFFFFFFFFu, ss, o);
    float inv = 1.0f / fmaxf(sqrtf(ss), 1e-12f);

    union { __nv_bfloat162 h[4]; uint4 u; } pack;
    pack.h[0] = __floats2bfloat162_rn(v0.x*inv, v0.y*inv);
    pack.h[1] = __floats2bfloat162_rn(v0.z*inv, v0.w*inv);
    pack.h[2] = __floats2bfloat162_rn(v1.x*inv, v1.y*inv);
    pack.h[3] = __floats2bfloat162_rn(v1.z*inv, v1.w*inv);
    reinterpret_cast<uint4*>(g_Fn)[row * (F_DIM/8) + lane] = pack.u;
}

// ---------------------------------------------------------------------------
// Kernel 2: L2-normalize prototypes -> bf16, zero-pad rows [1000,1024)
// ---------------------------------------------------------------------------
__global__ void norm_protos_kernel(const float* __restrict__ proto) {
    int gtid = blockIdx.x * blockDim.x + threadIdx.x;
    int row  = gtid >> 5;
    int lane = gtid & 31;
    if (row >= C_PAD) return;

    if (row >= C_COLS) {
        uint4 z = {0u, 0u, 0u, 0u};
        reinterpret_cast<uint4*>(g_Pn)[row * (F_DIM/8) + lane] = z;
        return;
    }
    const float4* src = reinterpret_cast<const float4*>(proto + (size_t)row * F_DIM);
    float4 v0 = src[lane * 2 + 0];
    float4 v1 = src[lane * 2 + 1];

    float ss = v0.x*v0.x + v0.y*v0.y + v0.z*v0.z + v0.w*v0.w
             + v1.x*v1.x + v1.y*v1.y + v1.z*v1.z + v1.w*v1.w;
    #pragma unroll
    for (int o = 16; o; o >>= 1) ss += __shfl_xor_sync(0xFFFFFFFFu, ss, o);
    float inv = 1.0f / fmaxf(sqrtf(ss), 1e-12f);

    union { __nv_bfloat162 h[4]; uint4 u; } pack;
    pack.h[0] = __floats2bfloat162_rn(v0.x*inv, v0.y*inv);
    pack.h[1] = __floats2bfloat162_rn(v0.z*inv, v0.w*inv);
    pack.h[2] = __floats2bfloat162_rn(v1.x*inv, v1.y*inv);
    pack.h[3] = __floats2bfloat162_rn(v1.z*inv, v1.w*inv);
    reinterpret_cast<uint4*>(g_Pn)[row * (F_DIM/8) + lane] = pack.u;
}

// ---------------------------------------------------------------------------
// Kernel 3: fully-fused GEMM + epilogue.
// Each CTA: 32 feature rows x ALL 1024 classes, acc register-resident.
//   - A (32x256 bf16) smem-resident, SW-swizzled.
//   - B streamed: 8 chunks of 128 rows, double-buffered cp.async.
//   - Warp w (0..15): m-tile = w&1 (16 rows), col strip s = w>>1 (16 cols/chunk).
//   - Epilogue: iso = |ds|*sqrt(max(1-cos,0)); CTA-local row mean; write
//     -(iso+mean)/temp through swizzled smem stage, coalesced.
// ---------------------------------------------------------------------------
__global__ void __launch_bounds__(THREADS, 1)
fused_gemm_kernel(const float* __restrict__ dscale, const float* __restrict__ temp,
                  float* __restrict__ out) {
    extern __shared__ __align__(16) unsigned char smem[];
    const uint32_t smem_base = smem_u32(smem);

    const int tid  = threadIdx.x;
    const int lane = tid & 31;
    const int warp = tid >> 5;
    const int mt   = warp & 1;     // 0/1 -> rows 0-15 / 16-31
    const int s    = warp >> 1;    // col strip 0..7 (16 cols within each chunk)

    float* srow = reinterpret_cast<float*>(smem + SM_SROW);
    if (tid < BM) srow[tid] = 0.0f;

    // ---- Load A tile (32x256 bf16 = 32x32 uint4), swizzled ----
    {
        const uint4* gA = reinterpret_cast<const uint4*>(g_Fn) + (size_t)blockIdx.x * BM * 32;
        #pragma unroll
        for (int it = 0; it < 2; it++) {
            int i = it * THREADS + tid;
            int r = i >> 5, c = i & 31;
            *reinterpret_cast<uint4*>(smem + SM_A + r * 512 + ((c ^ (r & 7)) << 4)) = __ldg(&gA[i]);
        }
    }
    // ---- Prefetch B chunk 0 into buf0 ----
    const uint4* gB = reinterpret_cast<const uint4*>(g_Pn);
    {
        #pragma unroll
        for (int it = 0; it < 8; it++) {
            int idx = it * THREADS + tid;            // 0..4095
            int r = idx >> 5, c = idx & 31;
            uint32_t dst = smem_base + SM_B0 + r * 512 + ((c ^ (r & 7)) << 4);
            CP_ASYNC16(dst, gB + (size_t)r * 32 + c);
        }
        CP_COMMIT();
    }
    CP_WAIT0();
    __syncthreads();

    // ---- ldmatrix lane addressing ----
    const int a_row = mt * 16 + (lane & 15);
    const int a_h   = lane >> 4;
    const uint32_t aBase = smem_base + SM_A + a_row * 512;
    const int aXor = a_row & 7;

    const int b_n = (lane & 7) | ((lane & 16) >> 1);   // 0..15 within strip
    const int b_h = (lane >> 3) & 1;
    const int n_row = s * 16 + b_n;
    const uint32_t bRowOff = (uint32_t)(n_row * 512);
    const int bXor = n_row & 7;

    float acc[NCHUNK][2][4];
    #pragma unroll
    for (int j = 0; j < NCHUNK; j++)
        #pragma unroll
        for (int t = 0; t < 2; t++)
            #pragma unroll
            for (int i = 0; i < 4; i++) acc[j][t][i] = 0.0f;

    // ---- Main loop over 8 B chunks, double-buffered ----
    #pragma unroll
    for (int j = 0; j < NCHUNK; j++) {
        if (j < NCHUNK - 1) {
            uint32_t nb = smem_base + ((j & 1) ? SM_B0 : SM_B1);
            #pragma unroll
            for (int it = 0; it < 8; it++) {
                int idx = it * THREADS + tid;
                int r = idx >> 5, c = idx & 31;
                CP_ASYNC16(nb + r * 512 + ((c ^ (r & 7)) << 4),
                           gB + (size_t)((j + 1) * BNC + r) * 32 + c);
            }
            CP_COMMIT();
        }

        uint32_t buf = smem_base + ((j & 1) ? SM_B1 : SM_B0);
        uint32_t bBase = buf + bRowOff;

        #pragma unroll
        for (int k = 0; k < 16; k++) {
            uint32_t af[4], bf[4];
            ldsm_x4(af, aBase + (((2 * k + a_h) ^ aXor) << 4));
            ldsm_x4(bf, bBase + (((2 * k + b_h) ^ bXor) << 4));
            mma16816(acc[j][0], af, bf[0], bf[1]);
            mma16816(acc[j][1], af, bf[2], bf[3]);
        }

        if (j < NCHUNK - 1) {
            CP_WAIT0();
            __syncthreads();
        }
    }

    // ---- Epilogue phase 1: iso + masked row sums ----
    const float ads = fabsf(__ldg(dscale));
    const float it_ = 1.0f / __ldg(temp);
    const int tr = lane >> 2;            // 0..7
    const int tc = (lane & 3) * 2;       // 0,2,4,6

    float rs0 = 0.0f, rs1 = 0.0f;
    #pragma unroll
    for (int j = 0; j < NCHUNK; j++) {
        #pragma unroll
        for (int t = 0; t < 2; t++) {
            int cb = j * 128 + s * 16 + t * 8 + tc;
            float i0 = ads * fsqrt_ap(fmaxf(1.0f - acc[j][t][0], 0.0f));
            float i1 = ads * fsqrt_ap(fmaxf(1.0f - acc[j][t][1], 0.0f));
            float i2 = ads * fsqrt_ap(fmaxf(1.0f - acc[j][t][2], 0.0f));
            float i3 = ads * fsqrt_ap(fmaxf(1.0f - acc[j][t][3], 0.0f));
            acc[j][t][0] = i0; acc[j][t][1] = i1;
            acc[j][t][2] = i2; acc[j][t][3] = i3;
            if (cb < C_COLS) {            // cb even, C_COLS even: pair never straddles
                rs0 += i0 + i1;
                rs1 += i2 + i3;
            }
        }
    }
    rs0 += __shfl_xor_sync(0xFFFFFFFFu, rs0, 1);
    rs0 += __shfl_xor_sync(0xFFFFFFFFu, rs0, 2);
    rs1 += __shfl_xor_sync(0xFFFFFFFFu, rs1, 1);
    rs1 += __shfl_xor_sync(0xFFFFFFFFu, rs1, 2);
    if ((lane & 3) == 0) {
        atomicAdd(&srow[mt * 16 + tr], rs0);
        atomicAdd(&srow[mt * 16 + tr + 8], rs1);
    }
    __syncthreads();      // all mma done (B bufs dead) + srow final

    // ---- Epilogue phase 2: final logits -> swizzled smem stage ----
    const float m0 = srow[mt * 16 + tr]     * (1.0f / (float)C_COLS);
    const float m1 = srow[mt * 16 + tr + 8] * (1.0f / (float)C_COLS);
    const uint32_t r0off = (uint32_t)(mt * 16 + tr) * 4096;
    const uint32_t r1off = r0off + 8 * 4096;
    const uint32_t x0 = ((uint32_t)((mt * 16 + tr) & 7)) << 4;
    const uint32_t x1 = ((uint32_t)((mt * 16 + tr + 8) & 7)) << 4;

    #pragma unroll
    for (int j = 0; j < NCHUNK; j++) {
        #pragma unroll
        for (int t = 0; t < 2; t++) {
            int cb = j * 128 + s * 16 + t * 8 + tc;
            float2 w0 = { -(acc[j][t][0] + m0) * it_, -(acc[j][t][1] + m0) * it_ };
            float2 w1 = { -(acc[j][t][2] + m1) * it_, -(acc[j][t][3] + m1) * it_ };
            uint32_t co = (uint32_t)(cb * 4);
            *reinterpret_cast<float2*>(smem + SM_STAGE + r0off + (co ^ x0)) = w0;
            *reinterpret_cast<float2*>(smem + SM_STAGE + r1off + (co ^ x1)) = w1;
        }
    }
    __syncthreads();

    // ---- Coalesced global write: 32 rows x 250 float4 ----
    const size_t grow0 = (size_t)blockIdx.x * BM;
    #pragma unroll
    for (int i = 0; i < 16; i++) {
        int fidx = i * THREADS + tid;        // 0..8191 over 32 rows x 256 f4
        int r  = fidx >> 8;
        int c4 = fidx & 255;
        if (c4 < C_COLS / 4) {
            uint32_t off = (uint32_t)r * 4096 + (((uint32_t)c4 << 4) ^ (((uint32_t)(r & 7)) << 4));
            float4 v = *reinterpret_cast<float4*>(smem + SM_STAGE + off);
            *reinterpret_cast<float4*>(out + (grow0 + r) * C_COLS + c4 * 4) = v;
        }
    }
}

// ---------------------------------------------------------------------------
extern "C" void kernel_launch(void* const* d_in, const int* in_sizes, int n_in,
                              void* d_out, int out_size) {
    const float* feat  = (const float*)d_in[0];
    const float* proto = (const float*)d_in[1];
    const float* dsc   = (const float*)d_in[2];
    const float* temp  = (const float*)d_in[3];
    float* out = (float*)d_out;

    cudaFuncSetAttribute(fused_gemm_kernel,
                         cudaFuncAttributeMaxDynamicSharedMemorySize, SM_TOTAL);

    norm_features_kernel<<<B_ROWS / 8, 256>>>(feat);
    norm_protos_kernel<<<C_PAD / 8, 256>>>(proto);
    fused_gemm_kernel<<<B_ROWS / BM, THREADS, SM_TOTAL>>>(dsc, temp, out);
}

// round 9
// speedup vs baseline: 1.4787x; 1.0845x over previous
#include <cuda_runtime.h>
#include <cuda_bf16.h>
#include <cstdint>

#define B_ROWS 32768
#define C_COLS 1000
#define C_PAD  1024
#define F_DIM  256

#define BM      32      // output rows per CTA
#define BNC     128     // B chunk rows (output cols) per stage
#define NCHUNK  8       // 1024 / 128
#define THREADS 512     // 16 warps

// SMEM layout (dynamic)
#define SM_A     0                       // 32 rows x 512B swizzled      = 16KB
#define SM_SROW  16384                   // 32 floats row sums
#define SM_B0    17408                   // chunk buffer 0: 128 x 512B   = 64KB
#define SM_B1    (17408 + 65536)         // chunk buffer 1               = 64KB
#define SM_TOTAL (17408 + 131072)        // 148480 B

// Scratch (device global — no allocation allowed)
__device__ __align__(16) __nv_bfloat16 g_Pn[(size_t)C_PAD * F_DIM];

// ---------------------------------------------------------------------------
// helpers
// ---------------------------------------------------------------------------
__device__ __forceinline__ uint32_t smem_u32(const void* p) {
    uint32_t a;
    asm("{ .reg .u64 t; cvta.to.shared.u64 t, %1; cvt.u32.u64 %0, t; }" : "=r"(a) : "l"(p));
    return a;
}
__device__ __forceinline__ void ldsm_x4(uint32_t* r, uint32_t addr) {
    asm volatile("ldmatrix.sync.aligned.m8n8.x4.shared.b16 {%0,%1,%2,%3}, [%4];\n"
        : "=r"(r[0]), "=r"(r[1]), "=r"(r[2]), "=r"(r[3]) : "r"(addr));
}
__device__ __forceinline__ void mma16816(float* c, const uint32_t* a, uint32_t b0, uint32_t b1) {
    asm volatile(
        "mma.sync.aligned.m16n8k16.row.col.f32.bf16.bf16.f32 "
        "{%0,%1,%2,%3}, {%4,%5,%6,%7}, {%8,%9}, {%0,%1,%2,%3};\n"
        : "+f"(c[0]), "+f"(c[1]), "+f"(c[2]), "+f"(c[3])
        : "r"(a[0]), "r"(a[1]), "r"(a[2]), "r"(a[3]), "r"(b0), "r"(b1));
}
__device__ __forceinline__ float fsqrt_ap(float x) {
    float r; asm("sqrt.approx.f32 %0, %1;" : "=f"(r) : "f"(x)); return r;
}
#define CP_ASYNC16(dst, src) \
    asm volatile("cp.async.cg.shared.global [%0], [%1], 16;" :: "r"(dst), "l"(src))
#define CP_COMMIT() asm volatile("cp.async.commit_group;" ::: "memory")
#define CP_WAIT0()  asm volatile("cp.async.wait_group 0;" ::: "memory")

// ---------------------------------------------------------------------------
// Kernel 1: L2-normalize prototypes -> bf16, zero-pad rows [1000,1024)
// ---------------------------------------------------------------------------
__global__ void norm_protos_kernel(const float* __restrict__ proto) {
    int gtid = blockIdx.x * blockDim.x + threadIdx.x;
    int row  = gtid >> 5;
    int lane = gtid & 31;
    if (row >= C_PAD) return;

    if (row >= C_COLS) {
        uint4 z = {0u, 0u, 0u, 0u};
        reinterpret_cast<uint4*>(g_Pn)[row * (F_DIM/8) + lane] = z;
        return;
    }
    const float4* src = reinterpret_cast<const float4*>(proto + (size_t)row * F_DIM);
    float4 v0 = src[lane * 2 + 0];
    float4 v1 = src[lane * 2 + 1];

    float ss = v0.x*v0.x + v0.y*v0.y + v0.z*v0.z + v0.w*v0.w
             + v1.x*v1.x + v1.y*v1.y + v1.z*v1.z + v1.w*v1.w;
    #pragma unroll
    for (int o = 16; o; o >>= 1) ss += __shfl_xor_sync(0xFFFFFFFFu, ss, o);
    float inv = 1.0f / fmaxf(sqrtf(ss), 1e-12f);

    union { __nv_bfloat162 h[4]; uint4 u; } pack;
    pack.h[0] = __floats2bfloat162_rn(v0.x*inv, v0.y*inv);
    pack.h[1] = __floats2bfloat162_rn(v0.z*inv, v0.w*inv);
    pack.h[2] = __floats2bfloat162_rn(v1.x*inv, v1.y*inv);
    pack.h[3] = __floats2bfloat162_rn(v1.z*inv, v1.w*inv);
    reinterpret_cast<uint4*>(g_Pn)[row * (F_DIM/8) + lane] = pack.u;
}

// ---------------------------------------------------------------------------
// Kernel 2: fully-fused normalize(A) + GEMM + epilogue.
// Each CTA: 32 feature rows x ALL 1024 classes, acc register-resident.
//   - A: raw floats loaded from gmem, L2-normalized in-CTA -> swizzled smem bf16
//     (overlapped with the B chunk-0 cp.async prefetch).
//   - B streamed: 8 chunks of 128 rows, double-buffered cp.async.
//   - Warp w (0..15): m-tile = w&1 (16 rows), col strip s = w>>1 (16 cols/chunk).
//   - Epilogue: iso = |ds|*sqrt(max(1-cos,0)); CTA-local row mean;
//     direct float2 stores of -(iso+mean)/temp.
// ---------------------------------------------------------------------------
__global__ void __launch_bounds__(THREADS, 1)
fused_gemm_kernel(const float* __restrict__ feat,
                  const float* __restrict__ dscale, const float* __restrict__ temp,
                  float* __restrict__ out) {
    extern __shared__ __align__(16) unsigned char smem[];
    const uint32_t smem_base = smem_u32(smem);

    const int tid  = threadIdx.x;
    const int lane = tid & 31;
    const int warp = tid >> 5;
    const int mt   = warp & 1;     // 0/1 -> rows 0-15 / 16-31
    const int s    = warp >> 1;    // col strip 0..7 (16 cols within each chunk)

    float* srow = reinterpret_cast<float*>(smem + SM_SROW);
    if (tid < BM) srow[tid] = 0.0f;

    // ---- Prefetch B chunk 0 into buf0 (issued first: overlaps A normalize) ----
    const uint4* gB = reinterpret_cast<const uint4*>(g_Pn);
    {
        #pragma unroll
        for (int it = 0; it < 8; it++) {
            int idx = it * THREADS + tid;            // 0..4095
            int r = idx >> 5, c = idx & 31;
            uint32_t dst = smem_base + SM_B0 + r * 512 + ((c ^ (r & 7)) << 4);
            CP_ASYNC16(dst, gB + (size_t)r * 32 + c);
        }
        CP_COMMIT();
    }

    // ---- Normalize A rows in-CTA: warp w handles rows 2w, 2w+1 ----
    {
        const float4* gF = reinterpret_cast<const float4*>(feat)
                         + (size_t)blockIdx.x * BM * (F_DIM / 4);
        #pragma unroll
        for (int rr = 0; rr < 2; rr++) {
            int r = warp * 2 + rr;
            float4 v0 = __ldg(&gF[r * 64 + lane * 2 + 0]);
            float4 v1 = __ldg(&gF[r * 64 + lane * 2 + 1]);
            float ss = v0.x*v0.x + v0.y*v0.y + v0.z*v0.z + v0.w*v0.w
                     + v1.x*v1.x + v1.y*v1.y + v1.z*v1.z + v1.w*v1.w;
            #pragma unroll
            for (int o = 16; o; o >>= 1) ss += __shfl_xor_sync(0xFFFFFFFFu, ss, o);
            float inv = 1.0f / fmaxf(sqrtf(ss), 1e-12f);

            union { __nv_bfloat162 h[4]; uint4 u; } pack;
            pack.h[0] = __floats2bfloat162_rn(v0.x*inv, v0.y*inv);
            pack.h[1] = __floats2bfloat162_rn(v0.z*inv, v0.w*inv);
            pack.h[2] = __floats2bfloat162_rn(v1.x*inv, v1.y*inv);
            pack.h[3] = __floats2bfloat162_rn(v1.z*inv, v1.w*inv);
            *reinterpret_cast<uint4*>(smem + SM_A + r * 512 + ((lane ^ (r & 7)) << 4)) = pack.u;
        }
    }
    CP_WAIT0();
    __syncthreads();

    // ---- ldmatrix lane addressing ----
    const int a_row = mt * 16 + (lane & 15);
    const int a_h   = lane >> 4;
    const uint32_t aBase = smem_base + SM_A + a_row * 512;
    const int aXor = a_row & 7;

    const int b_n = (lane & 7) | ((lane & 16) >> 1);   // 0..15 within strip
    const int b_h = (lane >> 3) & 1;
    const int n_row = s * 16 + b_n;
    const uint32_t bRowOff = (uint32_t)(n_row * 512);
    const int bXor = n_row & 7;

    float acc[NCHUNK][2][4];
    #pragma unroll
    for (int j = 0; j < NCHUNK; j++)
        #pragma unroll
        for (int t = 0; t < 2; t++)
            #pragma unroll
            for (int i = 0; i < 4; i++) acc[j][t][i] = 0.0f;

    // ---- Main loop over 8 B chunks, double-buffered ----
    #pragma unroll
    for (int j = 0; j < NCHUNK; j++) {
        if (j < NCHUNK - 1) {
            uint32_t nb = smem_base + ((j & 1) ? SM_B0 : SM_B1);
            #pragma unroll
            for (int it = 0; it < 8; it++) {
                int idx = it * THREADS + tid;
                int r = idx >> 5, c = idx & 31;
                CP_ASYNC16(nb + r * 512 + ((c ^ (r & 7)) << 4),
                           gB + (size_t)((j + 1) * BNC + r) * 32 + c);
            }
            CP_COMMIT();
        }

        uint32_t bBase = smem_base + ((j & 1) ? SM_B1 : SM_B0) + bRowOff;

        #pragma unroll
        for (int k = 0; k < 16; k++) {
            uint32_t af[4], bf[4];
            ldsm_x4(af, aBase + (((2 * k + a_h) ^ aXor) << 4));
            ldsm_x4(bf, bBase + (((2 * k + b_h) ^ bXor) << 4));
            mma16816(acc[j][0], af, bf[0], bf[1]);
            mma16816(acc[j][1], af, bf[2], bf[3]);
        }

        if (j < NCHUNK - 1) {
            CP_WAIT0();
            __syncthreads();
        }
    }

    // ---- Epilogue phase 1: iso + masked row sums ----
    const float ads = fabsf(__ldg(dscale));
    const float it_ = 1.0f / __ldg(temp);
    const int tr = lane >> 2;            // 0..7
    const int tc = (lane & 3) * 2;       // 0,2,4,6

    float rs0 = 0.0f, rs1 = 0.0f;
    #pragma unroll
    for (int j = 0; j < NCHUNK; j++) {
        #pragma unroll
        for (int t = 0; t < 2; t++) {
            int cb = j * 128 + s * 16 + t * 8 + tc;
            float i0 = ads * fsqrt_ap(fmaxf(1.0f - acc[j][t][0], 0.0f));
            float i1 = ads * fsqrt_ap(fmaxf(1.0f - acc[j][t][1], 0.0f));
            float i2 = ads * fsqrt_ap(fmaxf(1.0f - acc[j][t][2], 0.0f));
            float i3 = ads * fsqrt_ap(fmaxf(1.0f - acc[j][t][3], 0.0f));
            acc[j][t][0] = i0; acc[j][t][1] = i1;
            acc[j][t][2] = i2; acc[j][t][3] = i3;
            if (cb < C_COLS) {            // cb even, C_COLS even: pair never straddles
                rs0 += i0 + i1;
                rs1 += i2 + i3;
            }
        }
    }
    rs0 += __shfl_xor_sync(0xFFFFFFFFu, rs0, 1);
    rs0 += __shfl_xor_sync(0xFFFFFFFFu, rs0, 2);
    rs1 += __shfl_xor_sync(0xFFFFFFFFu, rs1, 1);
    rs1 += __shfl_xor_sync(0xFFFFFFFFu, rs1, 2);
    if ((lane & 3) == 0) {
        atomicAdd(&srow[mt * 16 + tr], rs0);
        atomicAdd(&srow[mt * 16 + tr + 8], rs1);
    }
    __syncthreads();

    // ---- Epilogue phase 2: direct global float2 stores ----
    const float m0 = srow[mt * 16 + tr]     * (1.0f / (float)C_COLS);
    const float m1 = srow[mt * 16 + tr + 8] * (1.0f / (float)C_COLS);
    const size_t grow0 = (size_t)blockIdx.x * BM;
    float* out_r0 = out + (grow0 + mt * 16 + tr)     * C_COLS;
    float* out_r1 = out + (grow0 + mt * 16 + tr + 8) * C_COLS;

    #pragma unroll
    for (int j = 0; j < NCHUNK; j++) {
        #pragma unroll
        for (int t = 0; t < 2; t++) {
            int cb = j * 128 + s * 16 + t * 8 + tc;
            if (cb < C_COLS) {
                float2 w0 = { -(acc[j][t][0] + m0) * it_, -(acc[j][t][1] + m0) * it_ };
                float2 w1 = { -(acc[j][t][2] + m1) * it_, -(acc[j][t][3] + m1) * it_ };
                *reinterpret_cast<float2*>(out_r0 + cb) = w0;
                *reinterpret_cast<float2*>(out_r1 + cb) = w1;
            }
        }
    }
}

// ---------------------------------------------------------------------------
extern "C" void kernel_launch(void* const* d_in, const int* in_sizes, int n_in,
                              void* d_out, int out_size) {
    const float* feat  = (const float*)d_in[0];
    const float* proto = (const float*)d_in[1];
    const float* dsc   = (const float*)d_in[2];
    const float* temp  = (const float*)d_in[3];
    float* out = (float*)d_out;

    cudaFuncSetAttribute(fused_gemm_kernel,
                         cudaFuncAttributeMaxDynamicSharedMemorySize, SM_TOTAL);

    norm_protos_kernel<<<C_PAD / 8, 256>>>(proto);
    fused_gemm_kernel<<<B_ROWS / BM, THREADS, SM_TOTAL>>>(feat, dsc, temp, out);
}